// round 14
// baseline (speedup 1.0000x reference)
#include <cuda_runtime.h>
#include <cuda_fp16.h>
#include <cstdint>

#define NN 50000
#define EE 800000
#define SCAN_T 2048

// ---------------- scratch (__device__ globals; allocation-free) ----------------
__device__ __half g_h[NN * 128];       // activations fp16 (gather-side)
__device__ __half g_agg[NN * 128];     // SpMM result fp16 (GEMM input)
__device__ float  g_nsrc[NN];
__device__ float  g_ndst[NN];
__device__ __align__(16) int g_dego[NN];
__device__ __align__(16) int g_degi[NN];
__device__ int    g_off[NN + 1];
__device__ int    g_cur[NN];
__device__ __align__(16) int g_csr[EE];
__device__ int    g_tsum[SCAN_T];
__device__ uint2  g_wfrag[3 * 4096 + 2048];   // HMMA B-frags: 3 layers + proj

#define MAXCHUNK 32   // max nodes per scan-thread (N <= SCAN_T * MAXCHUNK)

// ---------------- f32x2 packed helpers (Blackwell) ----------------
__device__ __forceinline__ unsigned long long pack2(float a, float b) {
    unsigned long long r;
    asm("mov.b64 %0, {%1, %2};" : "=l"(r) : "f"(a), "f"(b));
    return r;
}
__device__ __forceinline__ void unpack2(unsigned long long v, float& a, float& b) {
    asm("mov.b64 {%0, %1}, %2;" : "=f"(a), "=f"(b) : "l"(v));
}
__device__ __forceinline__ void addx2(unsigned long long& acc, unsigned long long v) {
    asm("add.rn.f32x2 %0, %0, %1;" : "+l"(acc) : "l"(v));
}
__device__ __forceinline__ void mulx2(unsigned long long& acc, unsigned long long v) {
    asm("mul.rn.f32x2 %0, %0, %1;" : "+l"(acc) : "l"(v));
}
__device__ __forceinline__ void acc_h2(unsigned long long& a0, unsigned long long& a1,
                                       uint2 v) {
    float2 f;
    f = __half22float2(*(const __half2*)&v.x);
    addx2(a0, pack2(f.x, f.y));
    f = __half22float2(*(const __half2*)&v.y);
    addx2(a1, pack2(f.x, f.y));
}

// mma.sync m16n8k16 row.col f16*f16+f32
__device__ __forceinline__ void hmma(float* c, uint32_t a0, uint32_t a1, uint32_t a2,
                                     uint32_t a3, uint32_t b0, uint32_t b1) {
    asm volatile(
        "mma.sync.aligned.m16n8k16.row.col.f32.f16.f16.f32 "
        "{%0,%1,%2,%3}, {%4,%5,%6,%7}, {%8,%9}, {%0,%1,%2,%3};"
        : "+f"(c[0]), "+f"(c[1]), "+f"(c[2]), "+f"(c[3])
        : "r"(a0), "r"(a1), "r"(a2), "r"(a3), "r"(b0), "r"(b1));
}

// ---------------- prep: weight frags + zero degree counters (merged) ----------------
__global__ void prep_kernel(const float* __restrict__ Wp, const float* __restrict__ Wl,
                            uint2* __restrict__ frag, int4* dego4, int4* degi4) {
    int i = blockIdx.x * blockDim.x + threadIdx.x;
    if (i < 12500) {
        int4 z = make_int4(0, 0, 0, 0);
        dego4[i] = z;
        degi4[i] = z;
    }
    if (i >= 3 * 4096 + 2048) return;
    const float* W;
    int lane, nt, kt;
    if (i < 12288) {
        lane = i & 31;
        nt = (i >> 5) & 15;
        kt = (i >> 9) & 7;
        W = Wl + (i >> 12) * 16384;
    } else {
        int j = i - 12288;
        lane = j & 31;
        nt = (j >> 5) & 15;
        kt = j >> 9;          // 0..3
        W = Wp;
    }
    int n = nt * 8 + (lane >> 2);
    int k0 = kt * 16 + (lane & 3) * 2;
    __half2 b0 = __floats2half2_rn(W[k0 * 128 + n], W[(k0 + 1) * 128 + n]);
    __half2 b1 = __floats2half2_rn(W[(k0 + 8) * 128 + n], W[(k0 + 9) * 128 + n]);
    uint2 u;
    u.x = *(uint32_t*)&b0;
    u.y = *(uint32_t*)&b1;
    frag[i] = u;
}

// ---------------- CSR build ----------------
__global__ void degree_kernel(const int* __restrict__ src, const int* __restrict__ dst,
                              int* dego, int* degi, int E) {
    int i = blockIdx.x * blockDim.x + threadIdx.x;
    int E8 = E >> 3;
    if (i < E8) {
        int4 sa = __ldg((const int4*)src + 2 * i);
        int4 sb = __ldg((const int4*)src + 2 * i + 1);
        int4 da = __ldg((const int4*)dst + 2 * i);
        int4 db = __ldg((const int4*)dst + 2 * i + 1);
        atomicAdd(&dego[sa.x], 1);
        atomicAdd(&dego[sa.y], 1);
        atomicAdd(&dego[sa.z], 1);
        atomicAdd(&dego[sa.w], 1);
        atomicAdd(&dego[sb.x], 1);
        atomicAdd(&dego[sb.y], 1);
        atomicAdd(&dego[sb.z], 1);
        atomicAdd(&dego[sb.w], 1);
        atomicAdd(&degi[da.x], 1);
        atomicAdd(&degi[da.y], 1);
        atomicAdd(&degi[da.z], 1);
        atomicAdd(&degi[da.w], 1);
        atomicAdd(&degi[db.x], 1);
        atomicAdd(&degi[db.y], 1);
        atomicAdd(&degi[db.z], 1);
        atomicAdd(&degi[db.w], 1);
    }
    if (i == 0) {
        for (int e = E8 << 3; e < E; e++) {
            atomicAdd(&dego[src[e]], 1);
            atomicAdd(&degi[dst[e]], 1);
        }
    }
}

// partial sums of degi per chunk PLUS norms; loads batched into registers first.
__global__ void partsum_norm_kernel(const int* __restrict__ degi,
                                    const int* __restrict__ dego,
                                    int* tsum, float* nsrc, float* ndst, int N) {
    int t = blockIdx.x * blockDim.x + threadIdx.x;
    if (t >= SCAN_T) return;
    int chunk = (N + SCAN_T - 1) / SCAN_T;
    int b = t * chunk;
    int cnt = min(chunk, N - b);
    if (cnt <= 0) { tsum[t] = 0; return; }

    int di[MAXCHUNK], doo[MAXCHUNK];
    #pragma unroll 8
    for (int k = 0; k < cnt; k++) di[k] = __ldg(&degi[b + k]);
    #pragma unroll 8
    for (int k = 0; k < cnt; k++) doo[k] = __ldg(&dego[b + k]);

    int s = 0;
    #pragma unroll 8
    for (int k = 0; k < cnt; k++) {
        s += di[k];
        ndst[b + k] = rsqrtf((float)max(di[k], 1));
        nsrc[b + k] = rsqrtf((float)max(doo[k], 1));
    }
    tsum[t] = s;
}

// merged scan + offset writeback; degi loads batched into registers first.
__global__ void scanwrite_kernel(const int* __restrict__ degi,
                                 const int* __restrict__ tsum,
                                 int* off, int* cur, int N) {
    __shared__ int sdata[SCAN_T];
    __shared__ int wsum[8];
    const int i = threadIdx.x;   // 0..255

    #pragma unroll
    for (int k = 0; k < 8; k++) sdata[k * 256 + i] = tsum[k * 256 + i];

    // prefetch this thread's degi chunk while the scan happens
    int g = blockIdx.x * 256 + i;
    int chunk = (N + SCAN_T - 1) / SCAN_T;
    int b = g * chunk;
    int cnt = min(chunk, N - b);
    if (cnt < 0) cnt = 0;
    int d[MAXCHUNK];
    #pragma unroll 8
    for (int k = 0; k < cnt; k++) d[k] = __ldg(&degi[b + k]);

    __syncthreads();

    // thread i owns partials [i*8, i*8+8)
    int base = i * 8;
    int loc[8];
    int p = 0;
    #pragma unroll
    for (int k = 0; k < 8; k++) {
        loc[k] = p;
        p += sdata[base + k];
    }
    int lane = i & 31, wid = i >> 5;
    int inc = p;
    #pragma unroll
    for (int dd = 1; dd < 32; dd <<= 1) {
        int u = __shfl_up_sync(0xffffffffu, inc, dd);
        if (lane >= dd) inc += u;
    }
    if (lane == 31) wsum[wid] = inc;
    __syncthreads();
    if (i == 0) {
        int run = 0;
        #pragma unroll
        for (int k = 0; k < 8; k++) {
            int v = wsum[k];
            wsum[k] = run;
            run += v;
        }
    }
    __syncthreads();
    int texcl = inc - p + wsum[wid];
    #pragma unroll
    for (int k = 0; k < 8; k++) sdata[base + k] = texcl + loc[k];
    __syncthreads();

    int run = sdata[g];
    #pragma unroll 8
    for (int k = 0; k < cnt; k++) {
        off[b + k] = run;
        cur[b + k] = run;
        run += d[k];
    }
    if (g == SCAN_T - 1) off[N] = run;
}

// 8 edges per thread: 8 independent ATOMG returns in flight.
__global__ void fill_kernel(const int* __restrict__ src, const int* __restrict__ dst,
                            int* cur, int* csr, int E) {
    int i = blockIdx.x * blockDim.x + threadIdx.x;
    int E8 = E >> 3;
    if (i < E8) {
        int4 sa = __ldg((const int4*)src + 2 * i);
        int4 sb = __ldg((const int4*)src + 2 * i + 1);
        int4 da = __ldg((const int4*)dst + 2 * i);
        int4 db = __ldg((const int4*)dst + 2 * i + 1);
        int p0 = atomicAdd(&cur[da.x], 1);
        int p1 = atomicAdd(&cur[da.y], 1);
        int p2 = atomicAdd(&cur[da.z], 1);
        int p3 = atomicAdd(&cur[da.w], 1);
        int p4 = atomicAdd(&cur[db.x], 1);
        int p5 = atomicAdd(&cur[db.y], 1);
        int p6 = atomicAdd(&cur[db.z], 1);
        int p7 = atomicAdd(&cur[db.w], 1);
        csr[p0] = sa.x;
        csr[p1] = sa.y;
        csr[p2] = sa.z;
        csr[p3] = sa.w;
        csr[p4] = sb.x;
        csr[p5] = sb.y;
        csr[p6] = sb.z;
        csr[p7] = sb.w;
    }
    if (i == 0) {
        for (int e = E8 << 3; e < E; e++) {
            int p = atomicAdd(&cur[dst[e]], 1);
            csr[p] = src[e];
        }
    }
}

// ---------------- pull SpMM: agg[d] = fp16( ndst[d] * sum_{s in in(d)} h[s] ) -----------
// csr indices loaded as int4 (aligned); dual f32x2 accumulator pairs.
__global__ void pull_kernel(const int* __restrict__ off, const int* __restrict__ csr,
                            const float* __restrict__ ndst,
                            const uint2* __restrict__ h2, uint2* __restrict__ agg2, int N) {
    int w = (blockIdx.x * blockDim.x + threadIdx.x) >> 5;
    int lane = threadIdx.x & 31;
    if (w >= N) return;
    int beg = __ldg(&off[w]);
    int end = __ldg(&off[w + 1]);

    unsigned long long a0 = pack2(0.f, 0.f), a1 = a0, b0 = a0, b1 = a0;

    int j = beg;
    // align j to 4 (csr is 16B-aligned globally)
    int pre = (4 - (beg & 3)) & 3;
    if (pre > end - beg) pre = end - beg;
    for (int k = 0; k < pre; k++, j++) {
        int s = __ldg(&csr[j]);
        acc_h2(a0, a1, __ldg(&h2[(long)s * 32 + lane]));
    }
    // main: 8 edges per iter, indices via 2x LDG.128 (uniform across warp)
    for (; j + 8 <= end; j += 8) {
        int4 ia = __ldg((const int4*)(csr + j));
        int4 ib = __ldg((const int4*)(csr + j + 4));
        uint2 v0 = __ldg(&h2[(long)ia.x * 32 + lane]);
        uint2 v1 = __ldg(&h2[(long)ia.y * 32 + lane]);
        uint2 v2 = __ldg(&h2[(long)ia.z * 32 + lane]);
        uint2 v3 = __ldg(&h2[(long)ia.w * 32 + lane]);
        uint2 v4 = __ldg(&h2[(long)ib.x * 32 + lane]);
        uint2 v5 = __ldg(&h2[(long)ib.y * 32 + lane]);
        uint2 v6 = __ldg(&h2[(long)ib.z * 32 + lane]);
        uint2 v7 = __ldg(&h2[(long)ib.w * 32 + lane]);
        acc_h2(a0, a1, v0);
        acc_h2(b0, b1, v1);
        acc_h2(a0, a1, v2);
        acc_h2(b0, b1, v3);
        acc_h2(a0, a1, v4);
        acc_h2(b0, b1, v5);
        acc_h2(a0, a1, v6);
        acc_h2(b0, b1, v7);
    }
    // 4-edge step
    if (j + 4 <= end) {
        int4 ia = __ldg((const int4*)(csr + j));
        uint2 v0 = __ldg(&h2[(long)ia.x * 32 + lane]);
        uint2 v1 = __ldg(&h2[(long)ia.y * 32 + lane]);
        uint2 v2 = __ldg(&h2[(long)ia.z * 32 + lane]);
        uint2 v3 = __ldg(&h2[(long)ia.w * 32 + lane]);
        acc_h2(a0, a1, v0);
        acc_h2(b0, b1, v1);
        acc_h2(a0, a1, v2);
        acc_h2(b0, b1, v3);
        j += 4;
    }
    for (; j < end; j++) {
        int s = __ldg(&csr[j]);
        acc_h2(a0, a1, __ldg(&h2[(long)s * 32 + lane]));
    }
    addx2(a0, b0);
    addx2(a1, b1);

    float nd = __ldg(&ndst[w]);
    unsigned long long nn = pack2(nd, nd);
    mulx2(a0, nn);
    mulx2(a1, nn);
    float4 o;
    unpack2(a0, o.x, o.y);
    unpack2(a1, o.z, o.w);
    __half2 p0 = __floats2half2_rn(o.x, o.y);
    __half2 p1 = __floats2half2_rn(o.z, o.w);
    uint2 st;
    st.x = *(uint32_t*)&p0;
    st.y = *(uint32_t*)&p1;
    agg2[(long)w * 32 + lane] = st;
}

// ---------------- HMMA GEMM: out = relu(X @ W + bias) * postscale ----------------
template <int KTILES, bool FP32IN, bool HALF_OUT>
__global__ void __launch_bounds__(256, 2)
gemm_mma_kernel(const void* __restrict__ Xv, const uint2* __restrict__ Wfrag,
                const float* __restrict__ B, const float* __restrict__ postscale,
                void* __restrict__ outv, int n) {
    constexpr int XPADH = KTILES * 16 + 8;
    constexpr int C4 = KTILES * 4;
    extern __shared__ char smraw[];
    __half* x_sh = (__half*)smraw;
    uint2* w_sh = (uint2*)(smraw + 128 * XPADH * 2);

    const int tx = threadIdx.x;
    const int row0 = blockIdx.x * 128;

    #pragma unroll
    for (int i = tx; i < KTILES * 512; i += 256) w_sh[i] = __ldg(&Wfrag[i]);

    #pragma unroll
    for (int i = tx; i < 128 * C4; i += 256) {
        int r = i / C4, c = i % C4;
        int gr = row0 + r;
        if (gr >= n) gr = n - 1;
        uint2 v;
        if (FP32IN) {
            float4 f = __ldg((const float4*)Xv + (long)gr * C4 + c);
            __half2 h0 = __floats2half2_rn(f.x, f.y);
            __half2 h1 = __floats2half2_rn(f.z, f.w);
            v.x = *(uint32_t*)&h0;
            v.y = *(uint32_t*)&h1;
        } else {
            v = __ldg((const uint2*)Xv + (long)gr * C4 + c);
        }
        *(uint2*)&x_sh[r * XPADH + c * 4] = v;
    }
    __syncthreads();

    const int w = tx >> 5;
    const int lane = tx & 31;
    const int rq = lane >> 2;
    const int kq = (lane & 3) * 2;

    float c[16][4];
    #pragma unroll
    for (int nt = 0; nt < 16; nt++)
        #pragma unroll
        for (int q = 0; q < 4; q++) c[nt][q] = 0.0f;

    #pragma unroll
    for (int kt = 0; kt < KTILES; kt++) {
        const __half* arow0 = &x_sh[(w * 16 + rq) * XPADH + kt * 16 + kq];
        const __half* arow1 = arow0 + 8 * XPADH;
        uint32_t a0 = *(const uint32_t*)arow0;
        uint32_t a1 = *(const uint32_t*)arow1;
        uint32_t a2 = *(const uint32_t*)(arow0 + 8);
        uint32_t a3 = *(const uint32_t*)(arow1 + 8);
        #pragma unroll
        for (int nt = 0; nt < 16; nt++) {
            uint2 b = w_sh[(kt * 16 + nt) * 32 + lane];
            hmma(c[nt], a0, a1, a2, a3, b.x, b.y);
        }
    }

    int r0 = row0 + w * 16 + rq;
    int r1 = r0 + 8;
    float sc0 = 1.0f, sc1 = 1.0f;
    if (postscale) {
        if (r0 < n) sc0 = __ldg(&postscale[r0]);
        if (r1 < n) sc1 = __ldg(&postscale[r1]);
    }
    #pragma unroll
    for (int nt = 0; nt < 16; nt++) {
        int col = nt * 8 + kq;
        float2 bv = *(const float2*)&B[col];
        float o00 = fmaxf(c[nt][0] + bv.x, 0.0f) * sc0;
        float o01 = fmaxf(c[nt][1] + bv.y, 0.0f) * sc0;
        float o10 = fmaxf(c[nt][2] + bv.x, 0.0f) * sc1;
        float o11 = fmaxf(c[nt][3] + bv.y, 0.0f) * sc1;
        if (HALF_OUT) {
            if (r0 < n) {
                __half2 p = __floats2half2_rn(o00, o01);
                *(uint32_t*)((__half*)outv + (long)r0 * 128 + col) = *(uint32_t*)&p;
            }
            if (r1 < n) {
                __half2 p = __floats2half2_rn(o10, o11);
                *(uint32_t*)((__half*)outv + (long)r1 * 128 + col) = *(uint32_t*)&p;
            }
        } else {
            if (r0 < n)
                *(float2*)((float*)outv + (long)r0 * 128 + col) = make_float2(o00, o01);
            if (r1 < n)
                *(float2*)((float*)outv + (long)r1 * 128 + col) = make_float2(o10, o11);
        }
    }
}

extern "C" void kernel_launch(void* const* d_in, const int* in_sizes, int n_in,
                              void* d_out, int out_size) {
    const float* x_raw = (const float*)d_in[0];
    const int*   src   = (const int*)d_in[1];
    const int*   dst   = (const int*)d_in[2];
    const float* Wp    = (const float*)d_in[3];
    const float* bp    = (const float*)d_in[4];
    const float* Wl    = (const float*)d_in[5];
    const float* bl    = (const float*)d_in[6];
    float* out = (float*)d_out;

    const int N = in_sizes[0] / 64;
    const int E = in_sizes[1];

    __half *h, *agg;
    float *nsrc, *ndst;
    int *dego, *degi, *off, *cur, *csr, *tsum;
    uint2* wfrag;
    cudaGetSymbolAddress((void**)&h, g_h);
    cudaGetSymbolAddress((void**)&agg, g_agg);
    cudaGetSymbolAddress((void**)&nsrc, g_nsrc);
    cudaGetSymbolAddress((void**)&ndst, g_ndst);
    cudaGetSymbolAddress((void**)&dego, g_dego);
    cudaGetSymbolAddress((void**)&degi, g_degi);
    cudaGetSymbolAddress((void**)&off, g_off);
    cudaGetSymbolAddress((void**)&cur, g_cur);
    cudaGetSymbolAddress((void**)&csr, g_csr);
    cudaGetSymbolAddress((void**)&tsum, g_tsum);
    cudaGetSymbolAddress((void**)&wfrag, g_wfrag);

    const int MMA_SMEM128 = 128 * 136 * 2 + 4096 * 8;
    const int MMA_SMEM64 = 128 * 72 * 2 + 2048 * 8;
    cudaFuncSetAttribute((const void*)gemm_mma_kernel<8, false, true>,
                         cudaFuncAttributeMaxDynamicSharedMemorySize, MMA_SMEM128);
    cudaFuncSetAttribute((const void*)gemm_mma_kernel<8, false, false>,
                         cudaFuncAttributeMaxDynamicSharedMemorySize, MMA_SMEM128);
    cudaFuncSetAttribute((const void*)gemm_mma_kernel<4, true, true>,
                         cudaFuncAttributeMaxDynamicSharedMemorySize, MMA_SMEM64);

    // 0) weight frags + zero degree counters (merged)
    prep_kernel<<<(3 * 4096 + 2048 + 255) / 256, 256>>>(
        Wp, Wl, wfrag, (int4*)dego, (int4*)degi);

    // 1) degrees -> norms + CSR(by dst)
    const int E8 = E >> 3;
    degree_kernel<<<(E8 + 255) / 256, 256>>>(src, dst, dego, degi, E);
    partsum_norm_kernel<<<SCAN_T / 256, 256>>>(degi, dego, tsum, nsrc, ndst, N);
    scanwrite_kernel<<<SCAN_T / 256, 256>>>(degi, tsum, off, cur, N);
    fill_kernel<<<(E8 + 255) / 256, 256>>>(src, dst, cur, csr, E);

    // 2) h = fp16( relu(x_raw @ Wp + bp) * norm_src )  — HMMA, K=64
    const int mma_blocks = (N + 127) / 128;
    gemm_mma_kernel<4, true, true><<<mma_blocks, 256, MMA_SMEM64>>>(
        x_raw, wfrag + 12288, bp, nsrc, h, N);

    // 3) layers: pull then HMMA GEMM
    const int pull_blocks = (N * 32 + 255) / 256;
    for (int l = 0; l < 3; l++) {
        pull_kernel<<<pull_blocks, 256>>>(off, csr, ndst, (const uint2*)h, (uint2*)agg, N);
        const uint2* wf = wfrag + (long)l * 4096;
        const float* bcur = bl + (long)l * 128;
        if (l == 2) {
            gemm_mma_kernel<8, false, false><<<mma_blocks, 256, MMA_SMEM128>>>(
                (const void*)agg, wf, bcur, nullptr, out, N);
        } else {
            gemm_mma_kernel<8, false, true><<<mma_blocks, 256, MMA_SMEM128>>>(
                (const void*)agg, wf, bcur, nsrc, h, N);
        }
    }
}

// round 15
// speedup vs baseline: 1.0462x; 1.0462x over previous
#include <cuda_runtime.h>
#include <cuda_fp16.h>
#include <cstdint>

#define NN 50000
#define EE 800000
#define SCAN_T 2048
#define CHUNK_U 25   // compile-time unroll bound: ceil(NN / SCAN_T)

// ---------------- scratch (__device__ globals; allocation-free) ----------------
__device__ __half g_h[NN * 128];       // activations fp16 (gather-side)
__device__ __half g_agg[NN * 128];     // SpMM result fp16 (GEMM input)
__device__ float  g_nsrc[NN];
__device__ float  g_ndst[NN];
__device__ __align__(16) int g_dego[NN];
__device__ __align__(16) int g_degi[NN];
__device__ int    g_off[NN + 1];
__device__ int    g_cur[NN];
__device__ int    g_csr[EE];
__device__ int    g_tsum[SCAN_T];
__device__ uint2  g_wfrag[3 * 4096 + 2048];   // HMMA B-frags: 3 layers + proj

// ---------------- f32x2 packed helpers (Blackwell) ----------------
__device__ __forceinline__ unsigned long long pack2(float a, float b) {
    unsigned long long r;
    asm("mov.b64 %0, {%1, %2};" : "=l"(r) : "f"(a), "f"(b));
    return r;
}
__device__ __forceinline__ void unpack2(unsigned long long v, float& a, float& b) {
    asm("mov.b64 {%0, %1}, %2;" : "=f"(a), "=f"(b) : "l"(v));
}
__device__ __forceinline__ void addx2(unsigned long long& acc, unsigned long long v) {
    asm("add.rn.f32x2 %0, %0, %1;" : "+l"(acc) : "l"(v));
}
__device__ __forceinline__ void mulx2(unsigned long long& acc, unsigned long long v) {
    asm("mul.rn.f32x2 %0, %0, %1;" : "+l"(acc) : "l"(v));
}
__device__ __forceinline__ void acc_h2(unsigned long long& a0, unsigned long long& a1,
                                       uint2 v) {
    float2 f;
    f = __half22float2(*(const __half2*)&v.x);
    addx2(a0, pack2(f.x, f.y));
    f = __half22float2(*(const __half2*)&v.y);
    addx2(a1, pack2(f.x, f.y));
}

// mma.sync m16n8k16 row.col f16*f16+f32
__device__ __forceinline__ void hmma(float* c, uint32_t a0, uint32_t a1, uint32_t a2,
                                     uint32_t a3, uint32_t b0, uint32_t b1) {
    asm volatile(
        "mma.sync.aligned.m16n8k16.row.col.f32.f16.f16.f32 "
        "{%0,%1,%2,%3}, {%4,%5,%6,%7}, {%8,%9}, {%0,%1,%2,%3};"
        : "+f"(c[0]), "+f"(c[1]), "+f"(c[2]), "+f"(c[3])
        : "r"(a0), "r"(a1), "r"(a2), "r"(a3), "r"(b0), "r"(b1));
}

// ---------------- prep: weight frags + zero degree counters (merged) ----------------
__global__ void prep_kernel(const float* __restrict__ Wp, const float* __restrict__ Wl,
                            uint2* __restrict__ frag, int4* dego4, int4* degi4) {
    int i = blockIdx.x * blockDim.x + threadIdx.x;
    if (i < 12500) {
        int4 z = make_int4(0, 0, 0, 0);
        dego4[i] = z;
        degi4[i] = z;
    }
    if (i >= 3 * 4096 + 2048) return;
    const float* W;
    int lane, nt, kt;
    if (i < 12288) {
        lane = i & 31;
        nt = (i >> 5) & 15;
        kt = (i >> 9) & 7;
        W = Wl + (i >> 12) * 16384;
    } else {
        int j = i - 12288;
        lane = j & 31;
        nt = (j >> 5) & 15;
        kt = j >> 9;          // 0..3
        W = Wp;
    }
    int n = nt * 8 + (lane >> 2);
    int k0 = kt * 16 + (lane & 3) * 2;
    __half2 b0 = __floats2half2_rn(W[k0 * 128 + n], W[(k0 + 1) * 128 + n]);
    __half2 b1 = __floats2half2_rn(W[(k0 + 8) * 128 + n], W[(k0 + 9) * 128 + n]);
    uint2 u;
    u.x = *(uint32_t*)&b0;
    u.y = *(uint32_t*)&b1;
    frag[i] = u;
}

// ---------------- CSR build ----------------
__global__ void degree_kernel(const int* __restrict__ src, const int* __restrict__ dst,
                              int* dego, int* degi, int E) {
    int i = blockIdx.x * blockDim.x + threadIdx.x;
    int E8 = E >> 3;
    if (i < E8) {
        int4 sa = __ldg((const int4*)src + 2 * i);
        int4 sb = __ldg((const int4*)src + 2 * i + 1);
        int4 da = __ldg((const int4*)dst + 2 * i);
        int4 db = __ldg((const int4*)dst + 2 * i + 1);
        atomicAdd(&dego[sa.x], 1);
        atomicAdd(&dego[sa.y], 1);
        atomicAdd(&dego[sa.z], 1);
        atomicAdd(&dego[sa.w], 1);
        atomicAdd(&dego[sb.x], 1);
        atomicAdd(&dego[sb.y], 1);
        atomicAdd(&dego[sb.z], 1);
        atomicAdd(&dego[sb.w], 1);
        atomicAdd(&degi[da.x], 1);
        atomicAdd(&degi[da.y], 1);
        atomicAdd(&degi[da.z], 1);
        atomicAdd(&degi[da.w], 1);
        atomicAdd(&degi[db.x], 1);
        atomicAdd(&degi[db.y], 1);
        atomicAdd(&degi[db.z], 1);
        atomicAdd(&degi[db.w], 1);
    }
    if (i == 0) {
        for (int e = E8 << 3; e < E; e++) {
            atomicAdd(&dego[src[e]], 1);
            atomicAdd(&degi[dst[e]], 1);
        }
    }
}

// partial sums + norms; fully-unrolled predicated body (static indices -> registers)
__global__ void partsum_norm_kernel(const int* __restrict__ degi,
                                    const int* __restrict__ dego,
                                    int* tsum, float* nsrc, float* ndst, int N) {
    int t = blockIdx.x * blockDim.x + threadIdx.x;
    if (t >= SCAN_T) return;
    int chunk = (N + SCAN_T - 1) / SCAN_T;
    int b = t * chunk;
    int cnt = min(chunk, N - b);
    if (cnt < 0) cnt = 0;

    int s = 0;
    #pragma unroll
    for (int k = 0; k < CHUNK_U; k++) {
        if (k < cnt) {
            int d = __ldg(&degi[b + k]);
            int o = __ldg(&dego[b + k]);
            s += d;
            ndst[b + k] = rsqrtf((float)max(d, 1));
            nsrc[b + k] = rsqrtf((float)max(o, 1));
        }
    }
    for (int k = CHUNK_U; k < cnt; k++) {   // safety tail for general N
        int d = __ldg(&degi[b + k]);
        s += d;
        ndst[b + k] = rsqrtf((float)max(d, 1));
        nsrc[b + k] = rsqrtf((float)max(dego[b + k], 1));
    }
    tsum[t] = s;
}

// merged scan + offset writeback; degi in a STATICALLY-indexed register array.
__global__ void scanwrite_kernel(const int* __restrict__ degi,
                                 const int* __restrict__ tsum,
                                 int* off, int* cur, int N) {
    __shared__ int sdata[SCAN_T];
    __shared__ int wsum[8];
    const int i = threadIdx.x;   // 0..255

    #pragma unroll
    for (int k = 0; k < 8; k++) sdata[k * 256 + i] = tsum[k * 256 + i];

    // prefetch this thread's degi chunk into registers (static unroll)
    int g = blockIdx.x * 256 + i;
    int chunk = (N + SCAN_T - 1) / SCAN_T;
    int b = g * chunk;
    int cnt = min(chunk, N - b);
    if (cnt < 0) cnt = 0;
    int d[CHUNK_U];
    #pragma unroll
    for (int k = 0; k < CHUNK_U; k++)
        d[k] = (k < cnt) ? __ldg(&degi[b + k]) : 0;

    __syncthreads();

    // thread i owns partials [i*8, i*8+8)
    int base = i * 8;
    int loc[8];
    int p = 0;
    #pragma unroll
    for (int k = 0; k < 8; k++) {
        loc[k] = p;
        p += sdata[base + k];
    }
    int lane = i & 31, wid = i >> 5;
    int inc = p;
    #pragma unroll
    for (int dd = 1; dd < 32; dd <<= 1) {
        int u = __shfl_up_sync(0xffffffffu, inc, dd);
        if (lane >= dd) inc += u;
    }
    if (lane == 31) wsum[wid] = inc;
    __syncthreads();
    if (i == 0) {
        int run = 0;
        #pragma unroll
        for (int k = 0; k < 8; k++) {
            int v = wsum[k];
            wsum[k] = run;
            run += v;
        }
    }
    __syncthreads();
    int texcl = inc - p + wsum[wid];
    #pragma unroll
    for (int k = 0; k < 8; k++) sdata[base + k] = texcl + loc[k];
    __syncthreads();

    int run = sdata[g];
    #pragma unroll
    for (int k = 0; k < CHUNK_U; k++) {
        if (k < cnt) {
            off[b + k] = run;
            cur[b + k] = run;
        }
        run += d[k];
    }
    for (int k = CHUNK_U; k < cnt; k++) {   // safety tail for general N
        off[b + k] = run;
        cur[b + k] = run;
        run += __ldg(&degi[b + k]);
    }
    if (g == SCAN_T - 1) off[N] = run;
}

// 8 edges per thread: 8 independent ATOMG returns in flight.
__global__ void fill_kernel(const int* __restrict__ src, const int* __restrict__ dst,
                            int* cur, int* csr, int E) {
    int i = blockIdx.x * blockDim.x + threadIdx.x;
    int E8 = E >> 3;
    if (i < E8) {
        int4 sa = __ldg((const int4*)src + 2 * i);
        int4 sb = __ldg((const int4*)src + 2 * i + 1);
        int4 da = __ldg((const int4*)dst + 2 * i);
        int4 db = __ldg((const int4*)dst + 2 * i + 1);
        int p0 = atomicAdd(&cur[da.x], 1);
        int p1 = atomicAdd(&cur[da.y], 1);
        int p2 = atomicAdd(&cur[da.z], 1);
        int p3 = atomicAdd(&cur[da.w], 1);
        int p4 = atomicAdd(&cur[db.x], 1);
        int p5 = atomicAdd(&cur[db.y], 1);
        int p6 = atomicAdd(&cur[db.z], 1);
        int p7 = atomicAdd(&cur[db.w], 1);
        csr[p0] = sa.x;
        csr[p1] = sa.y;
        csr[p2] = sa.z;
        csr[p3] = sa.w;
        csr[p4] = sb.x;
        csr[p5] = sb.y;
        csr[p6] = sb.z;
        csr[p7] = sb.w;
    }
    if (i == 0) {
        for (int e = E8 << 3; e < E; e++) {
            int p = atomicAdd(&cur[dst[e]], 1);
            csr[p] = src[e];
        }
    }
}

// ---------------- pull SpMM (R10/R13 version): agg[d] = fp16( ndst[d] * sum h[s] ) ------
__global__ void pull_kernel(const int* __restrict__ off, const int* __restrict__ csr,
                            const float* __restrict__ ndst,
                            const uint2* __restrict__ h2, uint2* __restrict__ agg2, int N) {
    int w = (blockIdx.x * blockDim.x + threadIdx.x) >> 5;
    int lane = threadIdx.x & 31;
    if (w >= N) return;
    int beg = __ldg(&off[w]);
    int end = __ldg(&off[w + 1]);

    unsigned long long a0 = pack2(0.f, 0.f), a1 = a0, b0 = a0, b1 = a0;

    int j = beg;
    for (; j + 8 <= end; j += 8) {
        int s0 = __ldg(&csr[j]);
        int s1 = __ldg(&csr[j + 1]);
        int s2 = __ldg(&csr[j + 2]);
        int s3 = __ldg(&csr[j + 3]);
        int s4 = __ldg(&csr[j + 4]);
        int s5 = __ldg(&csr[j + 5]);
        int s6 = __ldg(&csr[j + 6]);
        int s7 = __ldg(&csr[j + 7]);
        uint2 v0 = __ldg(&h2[(long)s0 * 32 + lane]);
        uint2 v1 = __ldg(&h2[(long)s1 * 32 + lane]);
        uint2 v2 = __ldg(&h2[(long)s2 * 32 + lane]);
        uint2 v3 = __ldg(&h2[(long)s3 * 32 + lane]);
        uint2 v4 = __ldg(&h2[(long)s4 * 32 + lane]);
        uint2 v5 = __ldg(&h2[(long)s5 * 32 + lane]);
        uint2 v6 = __ldg(&h2[(long)s6 * 32 + lane]);
        uint2 v7 = __ldg(&h2[(long)s7 * 32 + lane]);
        acc_h2(a0, a1, v0);
        acc_h2(b0, b1, v1);
        acc_h2(a0, a1, v2);
        acc_h2(b0, b1, v3);
        acc_h2(a0, a1, v4);
        acc_h2(b0, b1, v5);
        acc_h2(a0, a1, v6);
        acc_h2(b0, b1, v7);
    }
    for (; j < end; j++) {
        int s = __ldg(&csr[j]);
        acc_h2(a0, a1, __ldg(&h2[(long)s * 32 + lane]));
    }
    addx2(a0, b0);
    addx2(a1, b1);

    float nd = __ldg(&ndst[w]);
    unsigned long long nn = pack2(nd, nd);
    mulx2(a0, nn);
    mulx2(a1, nn);
    float4 o;
    unpack2(a0, o.x, o.y);
    unpack2(a1, o.z, o.w);
    __half2 p0 = __floats2half2_rn(o.x, o.y);
    __half2 p1 = __floats2half2_rn(o.z, o.w);
    uint2 st;
    st.x = *(uint32_t*)&p0;
    st.y = *(uint32_t*)&p1;
    agg2[(long)w * 32 + lane] = st;
}

// ---------------- HMMA GEMM: out = relu(X @ W + bias) * postscale ----------------
template <int KTILES, bool FP32IN, bool HALF_OUT>
__global__ void __launch_bounds__(256, 2)
gemm_mma_kernel(const void* __restrict__ Xv, const uint2* __restrict__ Wfrag,
                const float* __restrict__ B, const float* __restrict__ postscale,
                void* __restrict__ outv, int n) {
    constexpr int XPADH = KTILES * 16 + 8;
    constexpr int C4 = KTILES * 4;
    extern __shared__ char smraw[];
    __half* x_sh = (__half*)smraw;
    uint2* w_sh = (uint2*)(smraw + 128 * XPADH * 2);

    const int tx = threadIdx.x;
    const int row0 = blockIdx.x * 128;

    #pragma unroll
    for (int i = tx; i < KTILES * 512; i += 256) w_sh[i] = __ldg(&Wfrag[i]);

    #pragma unroll
    for (int i = tx; i < 128 * C4; i += 256) {
        int r = i / C4, c = i % C4;
        int gr = row0 + r;
        if (gr >= n) gr = n - 1;
        uint2 v;
        if (FP32IN) {
            float4 f = __ldg((const float4*)Xv + (long)gr * C4 + c);
            __half2 h0 = __floats2half2_rn(f.x, f.y);
            __half2 h1 = __floats2half2_rn(f.z, f.w);
            v.x = *(uint32_t*)&h0;
            v.y = *(uint32_t*)&h1;
        } else {
            v = __ldg((const uint2*)Xv + (long)gr * C4 + c);
        }
        *(uint2*)&x_sh[r * XPADH + c * 4] = v;
    }
    __syncthreads();

    const int w = tx >> 5;
    const int lane = tx & 31;
    const int rq = lane >> 2;
    const int kq = (lane & 3) * 2;

    float c[16][4];
    #pragma unroll
    for (int nt = 0; nt < 16; nt++)
        #pragma unroll
        for (int q = 0; q < 4; q++) c[nt][q] = 0.0f;

    #pragma unroll
    for (int kt = 0; kt < KTILES; kt++) {
        const __half* arow0 = &x_sh[(w * 16 + rq) * XPADH + kt * 16 + kq];
        const __half* arow1 = arow0 + 8 * XPADH;
        uint32_t a0 = *(const uint32_t*)arow0;
        uint32_t a1 = *(const uint32_t*)arow1;
        uint32_t a2 = *(const uint32_t*)(arow0 + 8);
        uint32_t a3 = *(const uint32_t*)(arow1 + 8);
        #pragma unroll
        for (int nt = 0; nt < 16; nt++) {
            uint2 b = w_sh[(kt * 16 + nt) * 32 + lane];
            hmma(c[nt], a0, a1, a2, a3, b.x, b.y);
        }
    }

    int r0 = row0 + w * 16 + rq;
    int r1 = r0 + 8;
    float sc0 = 1.0f, sc1 = 1.0f;
    if (postscale) {
        if (r0 < n) sc0 = __ldg(&postscale[r0]);
        if (r1 < n) sc1 = __ldg(&postscale[r1]);
    }
    #pragma unroll
    for (int nt = 0; nt < 16; nt++) {
        int col = nt * 8 + kq;
        float2 bv = *(const float2*)&B[col];
        float o00 = fmaxf(c[nt][0] + bv.x, 0.0f) * sc0;
        float o01 = fmaxf(c[nt][1] + bv.y, 0.0f) * sc0;
        float o10 = fmaxf(c[nt][2] + bv.x, 0.0f) * sc1;
        float o11 = fmaxf(c[nt][3] + bv.y, 0.0f) * sc1;
        if (HALF_OUT) {
            if (r0 < n) {
                __half2 p = __floats2half2_rn(o00, o01);
                *(uint32_t*)((__half*)outv + (long)r0 * 128 + col) = *(uint32_t*)&p;
            }
            if (r1 < n) {
                __half2 p = __floats2half2_rn(o10, o11);
                *(uint32_t*)((__half*)outv + (long)r1 * 128 + col) = *(uint32_t*)&p;
            }
        } else {
            if (r0 < n)
                *(float2*)((float*)outv + (long)r0 * 128 + col) = make_float2(o00, o01);
            if (r1 < n)
                *(float2*)((float*)outv + (long)r1 * 128 + col) = make_float2(o10, o11);
        }
    }
}

extern "C" void kernel_launch(void* const* d_in, const int* in_sizes, int n_in,
                              void* d_out, int out_size) {
    const float* x_raw = (const float*)d_in[0];
    const int*   src   = (const int*)d_in[1];
    const int*   dst   = (const int*)d_in[2];
    const float* Wp    = (const float*)d_in[3];
    const float* bp    = (const float*)d_in[4];
    const float* Wl    = (const float*)d_in[5];
    const float* bl    = (const float*)d_in[6];
    float* out = (float*)d_out;

    const int N = in_sizes[0] / 64;
    const int E = in_sizes[1];

    __half *h, *agg;
    float *nsrc, *ndst;
    int *dego, *degi, *off, *cur, *csr, *tsum;
    uint2* wfrag;
    cudaGetSymbolAddress((void**)&h, g_h);
    cudaGetSymbolAddress((void**)&agg, g_agg);
    cudaGetSymbolAddress((void**)&nsrc, g_nsrc);
    cudaGetSymbolAddress((void**)&ndst, g_ndst);
    cudaGetSymbolAddress((void**)&dego, g_dego);
    cudaGetSymbolAddress((void**)&degi, g_degi);
    cudaGetSymbolAddress((void**)&off, g_off);
    cudaGetSymbolAddress((void**)&cur, g_cur);
    cudaGetSymbolAddress((void**)&csr, g_csr);
    cudaGetSymbolAddress((void**)&tsum, g_tsum);
    cudaGetSymbolAddress((void**)&wfrag, g_wfrag);

    const int MMA_SMEM128 = 128 * 136 * 2 + 4096 * 8;
    const int MMA_SMEM64 = 128 * 72 * 2 + 2048 * 8;
    cudaFuncSetAttribute((const void*)gemm_mma_kernel<8, false, true>,
                         cudaFuncAttributeMaxDynamicSharedMemorySize, MMA_SMEM128);
    cudaFuncSetAttribute((const void*)gemm_mma_kernel<8, false, false>,
                         cudaFuncAttributeMaxDynamicSharedMemorySize, MMA_SMEM128);
    cudaFuncSetAttribute((const void*)gemm_mma_kernel<4, true, true>,
                         cudaFuncAttributeMaxDynamicSharedMemorySize, MMA_SMEM64);

    // 0) weight frags + zero degree counters (merged)
    prep_kernel<<<(3 * 4096 + 2048 + 255) / 256, 256>>>(
        Wp, Wl, wfrag, (int4*)dego, (int4*)degi);

    // 1) degrees -> norms + CSR(by dst)
    const int E8 = E >> 3;
    degree_kernel<<<(E8 + 255) / 256, 256>>>(src, dst, dego, degi, E);
    partsum_norm_kernel<<<SCAN_T / 256, 256>>>(degi, dego, tsum, nsrc, ndst, N);
    scanwrite_kernel<<<SCAN_T / 256, 256>>>(degi, tsum, off, cur, N);
    fill_kernel<<<(E8 + 255) / 256, 256>>>(src, dst, cur, csr, E);

    // 2) h = fp16( relu(x_raw @ Wp + bp) * norm_src )  — HMMA, K=64
    const int mma_blocks = (N + 127) / 128;
    gemm_mma_kernel<4, true, true><<<mma_blocks, 256, MMA_SMEM64>>>(
        x_raw, wfrag + 12288, bp, nsrc, h, N);

    // 3) layers: pull then HMMA GEMM
    const int pull_blocks = (N * 32 + 255) / 256;
    for (int l = 0; l < 3; l++) {
        pull_kernel<<<pull_blocks, 256>>>(off, csr, ndst, (const uint2*)h, (uint2*)agg, N);
        const uint2* wf = wfrag + (long)l * 4096;
        const float* bcur = bl + (long)l * 128;
        if (l == 2) {
            gemm_mma_kernel<8, false, false><<<mma_blocks, 256, MMA_SMEM128>>>(
                (const void*)agg, wf, bcur, nullptr, out, N);
        } else {
            gemm_mma_kernel<8, false, true><<<mma_blocks, 256, MMA_SMEM128>>>(
                (const void*)agg, wf, bcur, nsrc, h, N);
        }
    }
}

// round 16
// speedup vs baseline: 1.0727x; 1.0254x over previous
#include <cuda_runtime.h>
#include <cuda_fp16.h>
#include <cstdint>

#define NN 50000
#define EE 800000
#define SCAN_T 8192
#define CHUNK_U 7     // compile-time unroll bound: ceil(NN / SCAN_T)
#define PART_PER_T 32 // SCAN_T / 256

// ---------------- scratch (__device__ globals; allocation-free) ----------------
__device__ __half g_h[NN * 128];       // activations fp16 (gather-side)
__device__ __half g_agg[NN * 128];     // SpMM result fp16 (GEMM input)
__device__ float  g_nsrc[NN];
__device__ float  g_ndst[NN];
__device__ __align__(16) int g_dego[NN];
__device__ __align__(16) int g_degi[NN];
__device__ int    g_off[NN + 1];
__device__ int    g_cur[NN];
__device__ int    g_csr[EE];
__device__ int    g_tsum[SCAN_T];
__device__ uint2  g_wfrag[3 * 4096 + 2048];   // HMMA B-frags: 3 layers + proj

// ---------------- f32x2 packed helpers (Blackwell) ----------------
__device__ __forceinline__ unsigned long long pack2(float a, float b) {
    unsigned long long r;
    asm("mov.b64 %0, {%1, %2};" : "=l"(r) : "f"(a), "f"(b));
    return r;
}
__device__ __forceinline__ void unpack2(unsigned long long v, float& a, float& b) {
    asm("mov.b64 {%0, %1}, %2;" : "=f"(a), "=f"(b) : "l"(v));
}
__device__ __forceinline__ void addx2(unsigned long long& acc, unsigned long long v) {
    asm("add.rn.f32x2 %0, %0, %1;" : "+l"(acc) : "l"(v));
}
__device__ __forceinline__ void mulx2(unsigned long long& acc, unsigned long long v) {
    asm("mul.rn.f32x2 %0, %0, %1;" : "+l"(acc) : "l"(v));
}
__device__ __forceinline__ void acc_h2(unsigned long long& a0, unsigned long long& a1,
                                       uint2 v) {
    float2 f;
    f = __half22float2(*(const __half2*)&v.x);
    addx2(a0, pack2(f.x, f.y));
    f = __half22float2(*(const __half2*)&v.y);
    addx2(a1, pack2(f.x, f.y));
}

// mma.sync m16n8k16 row.col f16*f16+f32
__device__ __forceinline__ void hmma(float* c, uint32_t a0, uint32_t a1, uint32_t a2,
                                     uint32_t a3, uint32_t b0, uint32_t b1) {
    asm volatile(
        "mma.sync.aligned.m16n8k16.row.col.f32.f16.f16.f32 "
        "{%0,%1,%2,%3}, {%4,%5,%6,%7}, {%8,%9}, {%0,%1,%2,%3};"
        : "+f"(c[0]), "+f"(c[1]), "+f"(c[2]), "+f"(c[3])
        : "r"(a0), "r"(a1), "r"(a2), "r"(a3), "r"(b0), "r"(b1));
}

// ---------------- prep: weight frags + zero degree counters (merged) ----------------
__global__ void prep_kernel(const float* __restrict__ Wp, const float* __restrict__ Wl,
                            uint2* __restrict__ frag, int4* dego4, int4* degi4) {
    int i = blockIdx.x * blockDim.x + threadIdx.x;
    if (i < 12500) {
        int4 z = make_int4(0, 0, 0, 0);
        dego4[i] = z;
        degi4[i] = z;
    }
    if (i >= 3 * 4096 + 2048) return;
    const float* W;
    int lane, nt, kt;
    if (i < 12288) {
        lane = i & 31;
        nt = (i >> 5) & 15;
        kt = (i >> 9) & 7;
        W = Wl + (i >> 12) * 16384;
    } else {
        int j = i - 12288;
        lane = j & 31;
        nt = (j >> 5) & 15;
        kt = j >> 9;          // 0..3
        W = Wp;
    }
    int n = nt * 8 + (lane >> 2);
    int k0 = kt * 16 + (lane & 3) * 2;
    __half2 b0 = __floats2half2_rn(W[k0 * 128 + n], W[(k0 + 1) * 128 + n]);
    __half2 b1 = __floats2half2_rn(W[(k0 + 8) * 128 + n], W[(k0 + 9) * 128 + n]);
    uint2 u;
    u.x = *(uint32_t*)&b0;
    u.y = *(uint32_t*)&b1;
    frag[i] = u;
}

// ---------------- CSR build ----------------
__global__ void degree_kernel(const int* __restrict__ src, const int* __restrict__ dst,
                              int* dego, int* degi, int E) {
    int i = blockIdx.x * blockDim.x + threadIdx.x;
    int E8 = E >> 3;
    if (i < E8) {
        int4 sa = __ldg((const int4*)src + 2 * i);
        int4 sb = __ldg((const int4*)src + 2 * i + 1);
        int4 da = __ldg((const int4*)dst + 2 * i);
        int4 db = __ldg((const int4*)dst + 2 * i + 1);
        atomicAdd(&dego[sa.x], 1);
        atomicAdd(&dego[sa.y], 1);
        atomicAdd(&dego[sa.z], 1);
        atomicAdd(&dego[sa.w], 1);
        atomicAdd(&dego[sb.x], 1);
        atomicAdd(&dego[sb.y], 1);
        atomicAdd(&dego[sb.z], 1);
        atomicAdd(&dego[sb.w], 1);
        atomicAdd(&degi[da.x], 1);
        atomicAdd(&degi[da.y], 1);
        atomicAdd(&degi[da.z], 1);
        atomicAdd(&degi[da.w], 1);
        atomicAdd(&degi[db.x], 1);
        atomicAdd(&degi[db.y], 1);
        atomicAdd(&degi[db.z], 1);
        atomicAdd(&degi[db.w], 1);
    }
    if (i == 0) {
        for (int e = E8 << 3; e < E; e++) {
            atomicAdd(&dego[src[e]], 1);
            atomicAdd(&degi[dst[e]], 1);
        }
    }
}

// partial sums + norms; 8192 threads, <=7 nodes each, fully unrolled
__global__ void partsum_norm_kernel(const int* __restrict__ degi,
                                    const int* __restrict__ dego,
                                    int* tsum, float* nsrc, float* ndst, int N) {
    int t = blockIdx.x * blockDim.x + threadIdx.x;
    if (t >= SCAN_T) return;
    int chunk = (N + SCAN_T - 1) / SCAN_T;
    int b = t * chunk;
    int cnt = min(chunk, N - b);
    if (cnt < 0) cnt = 0;

    int s = 0;
    #pragma unroll
    for (int k = 0; k < CHUNK_U; k++) {
        if (k < cnt) {
            int d = __ldg(&degi[b + k]);
            int o = __ldg(&dego[b + k]);
            s += d;
            ndst[b + k] = rsqrtf((float)max(d, 1));
            nsrc[b + k] = rsqrtf((float)max(o, 1));
        }
    }
    for (int k = CHUNK_U; k < cnt; k++) {   // safety tail for general N
        int d = __ldg(&degi[b + k]);
        s += d;
        ndst[b + k] = rsqrtf((float)max(d, 1));
        nsrc[b + k] = rsqrtf((float)max(dego[b + k], 1));
    }
    tsum[t] = s;
}

// merged scan + offset writeback: 32 blocks each redundantly scan all 8192
// partials in smem, then block bi writes node chunks for ids [bi*256, bi*256+256).
__global__ void scanwrite_kernel(const int* __restrict__ degi,
                                 const int* __restrict__ tsum,
                                 int* off, int* cur, int N) {
    __shared__ int sdata[SCAN_T];
    __shared__ int wsum[8];
    const int i = threadIdx.x;   // 0..255

    #pragma unroll
    for (int k = 0; k < PART_PER_T; k++) sdata[k * 256 + i] = tsum[k * 256 + i];

    // prefetch this thread's degi chunk into registers (static unroll)
    int g = blockIdx.x * 256 + i;
    int chunk = (N + SCAN_T - 1) / SCAN_T;
    int b = g * chunk;
    int cnt = min(chunk, N - b);
    if (cnt < 0) cnt = 0;
    int d[CHUNK_U];
    #pragma unroll
    for (int k = 0; k < CHUNK_U; k++)
        d[k] = (k < cnt) ? __ldg(&degi[b + k]) : 0;

    __syncthreads();

    // thread i owns partials [i*32, i*32+32)
    int base = i * PART_PER_T;
    int loc[PART_PER_T];
    int p = 0;
    #pragma unroll
    for (int k = 0; k < PART_PER_T; k++) {
        loc[k] = p;
        p += sdata[base + k];
    }
    int lane = i & 31, wid = i >> 5;
    int inc = p;
    #pragma unroll
    for (int dd = 1; dd < 32; dd <<= 1) {
        int u = __shfl_up_sync(0xffffffffu, inc, dd);
        if (lane >= dd) inc += u;
    }
    if (lane == 31) wsum[wid] = inc;
    __syncthreads();
    if (i == 0) {
        int run = 0;
        #pragma unroll
        for (int k = 0; k < 8; k++) {
            int v = wsum[k];
            wsum[k] = run;
            run += v;
        }
    }
    __syncthreads();
    int texcl = inc - p + wsum[wid];
    #pragma unroll
    for (int k = 0; k < PART_PER_T; k++) sdata[base + k] = texcl + loc[k];
    __syncthreads();

    int run = sdata[g];
    #pragma unroll
    for (int k = 0; k < CHUNK_U; k++) {
        if (k < cnt) {
            off[b + k] = run;
            cur[b + k] = run;
        }
        run += d[k];
    }
    for (int k = CHUNK_U; k < cnt; k++) {   // safety tail for general N
        off[b + k] = run;
        cur[b + k] = run;
        run += __ldg(&degi[b + k]);
    }
    if (g == SCAN_T - 1) off[N] = run;
}

// 8 edges per thread: 8 independent ATOMG returns in flight.
__global__ void fill_kernel(const int* __restrict__ src, const int* __restrict__ dst,
                            int* cur, int* csr, int E) {
    int i = blockIdx.x * blockDim.x + threadIdx.x;
    int E8 = E >> 3;
    if (i < E8) {
        int4 sa = __ldg((const int4*)src + 2 * i);
        int4 sb = __ldg((const int4*)src + 2 * i + 1);
        int4 da = __ldg((const int4*)dst + 2 * i);
        int4 db = __ldg((const int4*)dst + 2 * i + 1);
        int p0 = atomicAdd(&cur[da.x], 1);
        int p1 = atomicAdd(&cur[da.y], 1);
        int p2 = atomicAdd(&cur[da.z], 1);
        int p3 = atomicAdd(&cur[da.w], 1);
        int p4 = atomicAdd(&cur[db.x], 1);
        int p5 = atomicAdd(&cur[db.y], 1);
        int p6 = atomicAdd(&cur[db.z], 1);
        int p7 = atomicAdd(&cur[db.w], 1);
        csr[p0] = sa.x;
        csr[p1] = sa.y;
        csr[p2] = sa.z;
        csr[p3] = sa.w;
        csr[p4] = sb.x;
        csr[p5] = sb.y;
        csr[p6] = sb.z;
        csr[p7] = sb.w;
    }
    if (i == 0) {
        for (int e = E8 << 3; e < E; e++) {
            int p = atomicAdd(&cur[dst[e]], 1);
            csr[p] = src[e];
        }
    }
}

// ---------------- pull SpMM: agg[d] = fp16( ndst[d] * sum_{s in in(d)} h[s] ) -----------
__global__ void pull_kernel(const int* __restrict__ off, const int* __restrict__ csr,
                            const float* __restrict__ ndst,
                            const uint2* __restrict__ h2, uint2* __restrict__ agg2, int N) {
    int w = (blockIdx.x * blockDim.x + threadIdx.x) >> 5;
    int lane = threadIdx.x & 31;
    if (w >= N) return;
    int beg = __ldg(&off[w]);
    int end = __ldg(&off[w + 1]);

    unsigned long long a0 = pack2(0.f, 0.f), a1 = a0, b0 = a0, b1 = a0;

    int j = beg;
    for (; j + 8 <= end; j += 8) {
        int s0 = __ldg(&csr[j]);
        int s1 = __ldg(&csr[j + 1]);
        int s2 = __ldg(&csr[j + 2]);
        int s3 = __ldg(&csr[j + 3]);
        int s4 = __ldg(&csr[j + 4]);
        int s5 = __ldg(&csr[j + 5]);
        int s6 = __ldg(&csr[j + 6]);
        int s7 = __ldg(&csr[j + 7]);
        uint2 v0 = __ldg(&h2[(long)s0 * 32 + lane]);
        uint2 v1 = __ldg(&h2[(long)s1 * 32 + lane]);
        uint2 v2 = __ldg(&h2[(long)s2 * 32 + lane]);
        uint2 v3 = __ldg(&h2[(long)s3 * 32 + lane]);
        uint2 v4 = __ldg(&h2[(long)s4 * 32 + lane]);
        uint2 v5 = __ldg(&h2[(long)s5 * 32 + lane]);
        uint2 v6 = __ldg(&h2[(long)s6 * 32 + lane]);
        uint2 v7 = __ldg(&h2[(long)s7 * 32 + lane]);
        acc_h2(a0, a1, v0);
        acc_h2(b0, b1, v1);
        acc_h2(a0, a1, v2);
        acc_h2(b0, b1, v3);
        acc_h2(a0, a1, v4);
        acc_h2(b0, b1, v5);
        acc_h2(a0, a1, v6);
        acc_h2(b0, b1, v7);
    }
    for (; j < end; j++) {
        int s = __ldg(&csr[j]);
        acc_h2(a0, a1, __ldg(&h2[(long)s * 32 + lane]));
    }
    addx2(a0, b0);
    addx2(a1, b1);

    float nd = __ldg(&ndst[w]);
    unsigned long long nn = pack2(nd, nd);
    mulx2(a0, nn);
    mulx2(a1, nn);
    float4 o;
    unpack2(a0, o.x, o.y);
    unpack2(a1, o.z, o.w);
    __half2 p0 = __floats2half2_rn(o.x, o.y);
    __half2 p1 = __floats2half2_rn(o.z, o.w);
    uint2 st;
    st.x = *(uint32_t*)&p0;
    st.y = *(uint32_t*)&p1;
    agg2[(long)w * 32 + lane] = st;
}

// ---------------- HMMA GEMM: out = relu(X @ W + bias) * postscale ----------------
template <int KTILES, bool FP32IN, bool HALF_OUT>
__global__ void __launch_bounds__(256, 2)
gemm_mma_kernel(const void* __restrict__ Xv, const uint2* __restrict__ Wfrag,
                const float* __restrict__ B, const float* __restrict__ postscale,
                void* __restrict__ outv, int n) {
    constexpr int XPADH = KTILES * 16 + 8;
    constexpr int C4 = KTILES * 4;
    extern __shared__ char smraw[];
    __half* x_sh = (__half*)smraw;
    uint2* w_sh = (uint2*)(smraw + 128 * XPADH * 2);

    const int tx = threadIdx.x;
    const int row0 = blockIdx.x * 128;

    #pragma unroll
    for (int i = tx; i < KTILES * 512; i += 256) w_sh[i] = __ldg(&Wfrag[i]);

    #pragma unroll
    for (int i = tx; i < 128 * C4; i += 256) {
        int r = i / C4, c = i % C4;
        int gr = row0 + r;
        if (gr >= n) gr = n - 1;
        uint2 v;
        if (FP32IN) {
            float4 f = __ldg((const float4*)Xv + (long)gr * C4 + c);
            __half2 h0 = __floats2half2_rn(f.x, f.y);
            __half2 h1 = __floats2half2_rn(f.z, f.w);
            v.x = *(uint32_t*)&h0;
            v.y = *(uint32_t*)&h1;
        } else {
            v = __ldg((const uint2*)Xv + (long)gr * C4 + c);
        }
        *(uint2*)&x_sh[r * XPADH + c * 4] = v;
    }
    __syncthreads();

    const int w = tx >> 5;
    const int lane = tx & 31;
    const int rq = lane >> 2;
    const int kq = (lane & 3) * 2;

    float c[16][4];
    #pragma unroll
    for (int nt = 0; nt < 16; nt++)
        #pragma unroll
        for (int q = 0; q < 4; q++) c[nt][q] = 0.0f;

    #pragma unroll
    for (int kt = 0; kt < KTILES; kt++) {
        const __half* arow0 = &x_sh[(w * 16 + rq) * XPADH + kt * 16 + kq];
        const __half* arow1 = arow0 + 8 * XPADH;
        uint32_t a0 = *(const uint32_t*)arow0;
        uint32_t a1 = *(const uint32_t*)arow1;
        uint32_t a2 = *(const uint32_t*)(arow0 + 8);
        uint32_t a3 = *(const uint32_t*)(arow1 + 8);
        #pragma unroll
        for (int nt = 0; nt < 16; nt++) {
            uint2 b = w_sh[(kt * 16 + nt) * 32 + lane];
            hmma(c[nt], a0, a1, a2, a3, b.x, b.y);
        }
    }

    int r0 = row0 + w * 16 + rq;
    int r1 = r0 + 8;
    float sc0 = 1.0f, sc1 = 1.0f;
    if (postscale) {
        if (r0 < n) sc0 = __ldg(&postscale[r0]);
        if (r1 < n) sc1 = __ldg(&postscale[r1]);
    }
    #pragma unroll
    for (int nt = 0; nt < 16; nt++) {
        int col = nt * 8 + kq;
        float2 bv = *(const float2*)&B[col];
        float o00 = fmaxf(c[nt][0] + bv.x, 0.0f) * sc0;
        float o01 = fmaxf(c[nt][1] + bv.y, 0.0f) * sc0;
        float o10 = fmaxf(c[nt][2] + bv.x, 0.0f) * sc1;
        float o11 = fmaxf(c[nt][3] + bv.y, 0.0f) * sc1;
        if (HALF_OUT) {
            if (r0 < n) {
                __half2 p = __floats2half2_rn(o00, o01);
                *(uint32_t*)((__half*)outv + (long)r0 * 128 + col) = *(uint32_t*)&p;
            }
            if (r1 < n) {
                __half2 p = __floats2half2_rn(o10, o11);
                *(uint32_t*)((__half*)outv + (long)r1 * 128 + col) = *(uint32_t*)&p;
            }
        } else {
            if (r0 < n)
                *(float2*)((float*)outv + (long)r0 * 128 + col) = make_float2(o00, o01);
            if (r1 < n)
                *(float2*)((float*)outv + (long)r1 * 128 + col) = make_float2(o10, o11);
        }
    }
}

extern "C" void kernel_launch(void* const* d_in, const int* in_sizes, int n_in,
                              void* d_out, int out_size) {
    const float* x_raw = (const float*)d_in[0];
    const int*   src   = (const int*)d_in[1];
    const int*   dst   = (const int*)d_in[2];
    const float* Wp    = (const float*)d_in[3];
    const float* bp    = (const float*)d_in[4];
    const float* Wl    = (const float*)d_in[5];
    const float* bl    = (const float*)d_in[6];
    float* out = (float*)d_out;

    const int N = in_sizes[0] / 64;
    const int E = in_sizes[1];

    __half *h, *agg;
    float *nsrc, *ndst;
    int *dego, *degi, *off, *cur, *csr, *tsum;
    uint2* wfrag;
    cudaGetSymbolAddress((void**)&h, g_h);
    cudaGetSymbolAddress((void**)&agg, g_agg);
    cudaGetSymbolAddress((void**)&nsrc, g_nsrc);
    cudaGetSymbolAddress((void**)&ndst, g_ndst);
    cudaGetSymbolAddress((void**)&dego, g_dego);
    cudaGetSymbolAddress((void**)&degi, g_degi);
    cudaGetSymbolAddress((void**)&off, g_off);
    cudaGetSymbolAddress((void**)&cur, g_cur);
    cudaGetSymbolAddress((void**)&csr, g_csr);
    cudaGetSymbolAddress((void**)&tsum, g_tsum);
    cudaGetSymbolAddress((void**)&wfrag, g_wfrag);

    const int MMA_SMEM128 = 128 * 136 * 2 + 4096 * 8;
    const int MMA_SMEM64 = 128 * 72 * 2 + 2048 * 8;
    cudaFuncSetAttribute((const void*)gemm_mma_kernel<8, false, true>,
                         cudaFuncAttributeMaxDynamicSharedMemorySize, MMA_SMEM128);
    cudaFuncSetAttribute((const void*)gemm_mma_kernel<8, false, false>,
                         cudaFuncAttributeMaxDynamicSharedMemorySize, MMA_SMEM128);
    cudaFuncSetAttribute((const void*)gemm_mma_kernel<4, true, true>,
                         cudaFuncAttributeMaxDynamicSharedMemorySize, MMA_SMEM64);

    // 0) weight frags + zero degree counters (merged)
    prep_kernel<<<(3 * 4096 + 2048 + 255) / 256, 256>>>(
        Wp, Wl, wfrag, (int4*)dego, (int4*)degi);

    // 1) degrees -> norms + CSR(by dst)
    const int E8 = E >> 3;
    degree_kernel<<<(E8 + 255) / 256, 256>>>(src, dst, dego, degi, E);
    partsum_norm_kernel<<<SCAN_T / 256, 256>>>(degi, dego, tsum, nsrc, ndst, N);
    scanwrite_kernel<<<SCAN_T / 256, 256>>>(degi, tsum, off, cur, N);
    fill_kernel<<<(E8 + 255) / 256, 256>>>(src, dst, cur, csr, E);

    // 2) h = fp16( relu(x_raw @ Wp + bp) * norm_src )  — HMMA, K=64
    const int mma_blocks = (N + 127) / 128;
    gemm_mma_kernel<4, true, true><<<mma_blocks, 256, MMA_SMEM64>>>(
        x_raw, wfrag + 12288, bp, nsrc, h, N);

    // 3) layers: pull then HMMA GEMM
    const int pull_blocks = (N * 32 + 255) / 256;
    for (int l = 0; l < 3; l++) {
        pull_kernel<<<pull_blocks, 256>>>(off, csr, ndst, (const uint2*)h, (uint2*)agg, N);
        const uint2* wf = wfrag + (long)l * 4096;
        const float* bcur = bl + (long)l * 128;
        if (l == 2) {
            gemm_mma_kernel<8, false, false><<<mma_blocks, 256, MMA_SMEM128>>>(
                (const void*)agg, wf, bcur, nullptr, out, N);
        } else {
            gemm_mma_kernel<8, false, true><<<mma_blocks, 256, MMA_SMEM128>>>(
                (const void*)agg, wf, bcur, nsrc, h, N);
        }
    }
}

// round 17
// speedup vs baseline: 1.1032x; 1.0284x over previous
#include <cuda_runtime.h>
#include <cuda_fp16.h>
#include <cstdint>

#define NN 50000
#define EE 800000
#define SCAN_T 8192
#define CHUNK_U 7     // compile-time unroll bound: ceil(NN / SCAN_T)

// ---------------- scratch (__device__ globals; allocation-free) ----------------
__device__ __half g_h[NN * 128];       // activations fp16 (gather-side)
__device__ __half g_agg[NN * 128];     // SpMM result fp16 (GEMM input)
__device__ float  g_nsrc[NN];
__device__ float  g_ndst[NN];
__device__ __align__(16) int g_dego[NN];
__device__ __align__(16) int g_degi[NN];
__device__ int    g_off[NN + 1];
__device__ int    g_cur[NN];
__device__ int    g_csr[EE];
__device__ int    g_tsum[SCAN_T];
__device__ int    g_btot[32];          // per-scan-block totals (SCAN_T/256)
__device__ uint2  g_wfrag[3 * 4096 + 2048];   // HMMA B-frags: 3 layers + proj

// ---------------- f32x2 packed helpers (Blackwell) ----------------
__device__ __forceinline__ unsigned long long pack2(float a, float b) {
    unsigned long long r;
    asm("mov.b64 %0, {%1, %2};" : "=l"(r) : "f"(a), "f"(b));
    return r;
}
__device__ __forceinline__ void unpack2(unsigned long long v, float& a, float& b) {
    asm("mov.b64 {%0, %1}, %2;" : "=f"(a), "=f"(b) : "l"(v));
}
__device__ __forceinline__ void addx2(unsigned long long& acc, unsigned long long v) {
    asm("add.rn.f32x2 %0, %0, %1;" : "+l"(acc) : "l"(v));
}
__device__ __forceinline__ void mulx2(unsigned long long& acc, unsigned long long v) {
    asm("mul.rn.f32x2 %0, %0, %1;" : "+l"(acc) : "l"(v));
}
__device__ __forceinline__ void acc_h2(unsigned long long& a0, unsigned long long& a1,
                                       uint2 v) {
    float2 f;
    f = __half22float2(*(const __half2*)&v.x);
    addx2(a0, pack2(f.x, f.y));
    f = __half22float2(*(const __half2*)&v.y);
    addx2(a1, pack2(f.x, f.y));
}

// mma.sync m16n8k16 row.col f16*f16+f32
__device__ __forceinline__ void hmma(float* c, uint32_t a0, uint32_t a1, uint32_t a2,
                                     uint32_t a3, uint32_t b0, uint32_t b1) {
    asm volatile(
        "mma.sync.aligned.m16n8k16.row.col.f32.f16.f16.f32 "
        "{%0,%1,%2,%3}, {%4,%5,%6,%7}, {%8,%9}, {%0,%1,%2,%3};"
        : "+f"(c[0]), "+f"(c[1]), "+f"(c[2]), "+f"(c[3])
        : "r"(a0), "r"(a1), "r"(a2), "r"(a3), "r"(b0), "r"(b1));
}

// ---------------- prep: weight frags + zero degree counters + zero btot ----------------
__global__ void prep_kernel(const float* __restrict__ Wp, const float* __restrict__ Wl,
                            uint2* __restrict__ frag, int4* dego4, int4* degi4,
                            int* btot) {
    int i = blockIdx.x * blockDim.x + threadIdx.x;
    if (i < 12500) {
        int4 z = make_int4(0, 0, 0, 0);
        dego4[i] = z;
        degi4[i] = z;
    }
    if (i < 32) btot[i] = 0;
    if (i >= 3 * 4096 + 2048) return;
    const float* W;
    int lane, nt, kt;
    if (i < 12288) {
        lane = i & 31;
        nt = (i >> 5) & 15;
        kt = (i >> 9) & 7;
        W = Wl + (i >> 12) * 16384;
    } else {
        int j = i - 12288;
        lane = j & 31;
        nt = (j >> 5) & 15;
        kt = j >> 9;          // 0..3
        W = Wp;
    }
    int n = nt * 8 + (lane >> 2);
    int k0 = kt * 16 + (lane & 3) * 2;
    __half2 b0 = __floats2half2_rn(W[k0 * 128 + n], W[(k0 + 1) * 128 + n]);
    __half2 b1 = __floats2half2_rn(W[(k0 + 8) * 128 + n], W[(k0 + 9) * 128 + n]);
    uint2 u;
    u.x = *(uint32_t*)&b0;
    u.y = *(uint32_t*)&b1;
    frag[i] = u;
}

// ---------------- CSR build ----------------
__global__ void degree_kernel(const int* __restrict__ src, const int* __restrict__ dst,
                              int* dego, int* degi, int E) {
    int i = blockIdx.x * blockDim.x + threadIdx.x;
    int E8 = E >> 3;
    if (i < E8) {
        int4 sa = __ldg((const int4*)src + 2 * i);
        int4 sb = __ldg((const int4*)src + 2 * i + 1);
        int4 da = __ldg((const int4*)dst + 2 * i);
        int4 db = __ldg((const int4*)dst + 2 * i + 1);
        atomicAdd(&dego[sa.x], 1);
        atomicAdd(&dego[sa.y], 1);
        atomicAdd(&dego[sa.z], 1);
        atomicAdd(&dego[sa.w], 1);
        atomicAdd(&dego[sb.x], 1);
        atomicAdd(&dego[sb.y], 1);
        atomicAdd(&dego[sb.z], 1);
        atomicAdd(&dego[sb.w], 1);
        atomicAdd(&degi[da.x], 1);
        atomicAdd(&degi[da.y], 1);
        atomicAdd(&degi[da.z], 1);
        atomicAdd(&degi[da.w], 1);
        atomicAdd(&degi[db.x], 1);
        atomicAdd(&degi[db.y], 1);
        atomicAdd(&degi[db.z], 1);
        atomicAdd(&degi[db.w], 1);
    }
    if (i == 0) {
        for (int e = E8 << 3; e < E; e++) {
            atomicAdd(&dego[src[e]], 1);
            atomicAdd(&degi[dst[e]], 1);
        }
    }
}

// partial sums + norms + per-scan-block totals via atomics
__global__ void partsum_norm_kernel(const int* __restrict__ degi,
                                    const int* __restrict__ dego,
                                    int* tsum, int* btot,
                                    float* nsrc, float* ndst, int N) {
    int t = blockIdx.x * blockDim.x + threadIdx.x;
    if (t >= SCAN_T) return;
    int chunk = (N + SCAN_T - 1) / SCAN_T;
    int b = t * chunk;
    int cnt = min(chunk, N - b);
    if (cnt < 0) cnt = 0;

    int s = 0;
    #pragma unroll
    for (int k = 0; k < CHUNK_U; k++) {
        if (k < cnt) {
            int d = __ldg(&degi[b + k]);
            int o = __ldg(&dego[b + k]);
            s += d;
            ndst[b + k] = rsqrtf((float)max(d, 1));
            nsrc[b + k] = rsqrtf((float)max(o, 1));
        }
    }
    for (int k = CHUNK_U; k < cnt; k++) {   // safety tail for general N
        int d = __ldg(&degi[b + k]);
        s += d;
        ndst[b + k] = rsqrtf((float)max(d, 1));
        nsrc[b + k] = rsqrtf((float)max(dego[b + k], 1));
    }
    tsum[t] = s;
    atomicAdd(&btot[t >> 8], s);
}

// hierarchical scan + offset writeback: block bi scans ONLY its 256 partials;
// global offset comes from a 32-wide reduce over btot[0..bi).
__global__ void scanwrite_kernel(const int* __restrict__ degi,
                                 const int* __restrict__ tsum,
                                 const int* __restrict__ btot,
                                 int* off, int* cur, int N) {
    __shared__ int wsum[8];
    __shared__ int blockoff_s;
    const int i = threadIdx.x;   // 0..255
    const int bi = blockIdx.x;   // 0..31
    const int g = bi * 256 + i;

    int p = __ldg(&tsum[g]);

    // prefetch this thread's degi chunk into registers (static unroll)
    int chunk = (N + SCAN_T - 1) / SCAN_T;
    int b = g * chunk;
    int cnt = min(chunk, N - b);
    if (cnt < 0) cnt = 0;
    int d[CHUNK_U];
    #pragma unroll
    for (int k = 0; k < CHUNK_U; k++)
        d[k] = (k < cnt) ? __ldg(&degi[b + k]) : 0;

    // intra-block inclusive scan of p
    int lane = i & 31, wid = i >> 5;
    int inc = p;
    #pragma unroll
    for (int dd = 1; dd < 32; dd <<= 1) {
        int u = __shfl_up_sync(0xffffffffu, inc, dd);
        if (lane >= dd) inc += u;
    }
    if (lane == 31) wsum[wid] = inc;

    // block offset: sum of btot[0..bi) by warp 0 (concurrent with wsum fill)
    if (i < 32) {
        int v = (i < bi) ? __ldg(&btot[i]) : 0;
        #pragma unroll
        for (int dd = 16; dd > 0; dd >>= 1)
            v += __shfl_down_sync(0xffffffffu, v, dd);
        if (i == 0) blockoff_s = v;
    }
    __syncthreads();
    if (i == 0) {
        int run = 0;
        #pragma unroll
        for (int k = 0; k < 8; k++) {
            int v = wsum[k];
            wsum[k] = run;
            run += v;
        }
    }
    __syncthreads();
    int excl = (inc - p) + wsum[wid] + blockoff_s;

    int run = excl;
    #pragma unroll
    for (int k = 0; k < CHUNK_U; k++) {
        if (k < cnt) {
            off[b + k] = run;
            cur[b + k] = run;
        }
        run += d[k];
    }
    for (int k = CHUNK_U; k < cnt; k++) {   // safety tail for general N
        off[b + k] = run;
        cur[b + k] = run;
        run += __ldg(&degi[b + k]);
    }
    if (g == SCAN_T - 1) off[N] = run;
}

// 8 edges per thread: 8 independent ATOMG returns in flight.
__global__ void fill_kernel(const int* __restrict__ src, const int* __restrict__ dst,
                            int* cur, int* csr, int E) {
    int i = blockIdx.x * blockDim.x + threadIdx.x;
    int E8 = E >> 3;
    if (i < E8) {
        int4 sa = __ldg((const int4*)src + 2 * i);
        int4 sb = __ldg((const int4*)src + 2 * i + 1);
        int4 da = __ldg((const int4*)dst + 2 * i);
        int4 db = __ldg((const int4*)dst + 2 * i + 1);
        int p0 = atomicAdd(&cur[da.x], 1);
        int p1 = atomicAdd(&cur[da.y], 1);
        int p2 = atomicAdd(&cur[da.z], 1);
        int p3 = atomicAdd(&cur[da.w], 1);
        int p4 = atomicAdd(&cur[db.x], 1);
        int p5 = atomicAdd(&cur[db.y], 1);
        int p6 = atomicAdd(&cur[db.z], 1);
        int p7 = atomicAdd(&cur[db.w], 1);
        csr[p0] = sa.x;
        csr[p1] = sa.y;
        csr[p2] = sa.z;
        csr[p3] = sa.w;
        csr[p4] = sb.x;
        csr[p5] = sb.y;
        csr[p6] = sb.z;
        csr[p7] = sb.w;
    }
    if (i == 0) {
        for (int e = E8 << 3; e < E; e++) {
            int p = atomicAdd(&cur[dst[e]], 1);
            csr[p] = src[e];
        }
    }
}

// ---------------- pull SpMM: agg[d] = fp16( ndst[d] * sum_{s in in(d)} h[s] ) -----------
__global__ void pull_kernel(const int* __restrict__ off, const int* __restrict__ csr,
                            const float* __restrict__ ndst,
                            const uint2* __restrict__ h2, uint2* __restrict__ agg2, int N) {
    int w = (blockIdx.x * blockDim.x + threadIdx.x) >> 5;
    int lane = threadIdx.x & 31;
    if (w >= N) return;
    int beg = __ldg(&off[w]);
    int end = __ldg(&off[w + 1]);

    unsigned long long a0 = pack2(0.f, 0.f), a1 = a0, b0 = a0, b1 = a0;

    int j = beg;
    for (; j + 8 <= end; j += 8) {
        int s0 = __ldg(&csr[j]);
        int s1 = __ldg(&csr[j + 1]);
        int s2 = __ldg(&csr[j + 2]);
        int s3 = __ldg(&csr[j + 3]);
        int s4 = __ldg(&csr[j + 4]);
        int s5 = __ldg(&csr[j + 5]);
        int s6 = __ldg(&csr[j + 6]);
        int s7 = __ldg(&csr[j + 7]);
        uint2 v0 = __ldg(&h2[(long)s0 * 32 + lane]);
        uint2 v1 = __ldg(&h2[(long)s1 * 32 + lane]);
        uint2 v2 = __ldg(&h2[(long)s2 * 32 + lane]);
        uint2 v3 = __ldg(&h2[(long)s3 * 32 + lane]);
        uint2 v4 = __ldg(&h2[(long)s4 * 32 + lane]);
        uint2 v5 = __ldg(&h2[(long)s5 * 32 + lane]);
        uint2 v6 = __ldg(&h2[(long)s6 * 32 + lane]);
        uint2 v7 = __ldg(&h2[(long)s7 * 32 + lane]);
        acc_h2(a0, a1, v0);
        acc_h2(b0, b1, v1);
        acc_h2(a0, a1, v2);
        acc_h2(b0, b1, v3);
        acc_h2(a0, a1, v4);
        acc_h2(b0, b1, v5);
        acc_h2(a0, a1, v6);
        acc_h2(b0, b1, v7);
    }
    for (; j < end; j++) {
        int s = __ldg(&csr[j]);
        acc_h2(a0, a1, __ldg(&h2[(long)s * 32 + lane]));
    }
    addx2(a0, b0);
    addx2(a1, b1);

    float nd = __ldg(&ndst[w]);
    unsigned long long nn = pack2(nd, nd);
    mulx2(a0, nn);
    mulx2(a1, nn);
    float4 o;
    unpack2(a0, o.x, o.y);
    unpack2(a1, o.z, o.w);
    __half2 p0 = __floats2half2_rn(o.x, o.y);
    __half2 p1 = __floats2half2_rn(o.z, o.w);
    uint2 st;
    st.x = *(uint32_t*)&p0;
    st.y = *(uint32_t*)&p1;
    agg2[(long)w * 32 + lane] = st;
}

// ---------------- HMMA GEMM: out = relu(X @ W + bias) * postscale ----------------
template <int KTILES, bool FP32IN, bool HALF_OUT>
__global__ void __launch_bounds__(256, 2)
gemm_mma_kernel(const void* __restrict__ Xv, const uint2* __restrict__ Wfrag,
                const float* __restrict__ B, const float* __restrict__ postscale,
                void* __restrict__ outv, int n) {
    constexpr int XPADH = KTILES * 16 + 8;
    constexpr int C4 = KTILES * 4;
    extern __shared__ char smraw[];
    __half* x_sh = (__half*)smraw;
    uint2* w_sh = (uint2*)(smraw + 128 * XPADH * 2);

    const int tx = threadIdx.x;
    const int row0 = blockIdx.x * 128;

    #pragma unroll
    for (int i = tx; i < KTILES * 512; i += 256) w_sh[i] = __ldg(&Wfrag[i]);

    #pragma unroll
    for (int i = tx; i < 128 * C4; i += 256) {
        int r = i / C4, c = i % C4;
        int gr = row0 + r;
        if (gr >= n) gr = n - 1;
        uint2 v;
        if (FP32IN) {
            float4 f = __ldg((const float4*)Xv + (long)gr * C4 + c);
            __half2 h0 = __floats2half2_rn(f.x, f.y);
            __half2 h1 = __floats2half2_rn(f.z, f.w);
            v.x = *(uint32_t*)&h0;
            v.y = *(uint32_t*)&h1;
        } else {
            v = __ldg((const uint2*)Xv + (long)gr * C4 + c);
        }
        *(uint2*)&x_sh[r * XPADH + c * 4] = v;
    }
    __syncthreads();

    const int w = tx >> 5;
    const int lane = tx & 31;
    const int rq = lane >> 2;
    const int kq = (lane & 3) * 2;

    float c[16][4];
    #pragma unroll
    for (int nt = 0; nt < 16; nt++)
        #pragma unroll
        for (int q = 0; q < 4; q++) c[nt][q] = 0.0f;

    #pragma unroll
    for (int kt = 0; kt < KTILES; kt++) {
        const __half* arow0 = &x_sh[(w * 16 + rq) * XPADH + kt * 16 + kq];
        const __half* arow1 = arow0 + 8 * XPADH;
        uint32_t a0 = *(const uint32_t*)arow0;
        uint32_t a1 = *(const uint32_t*)arow1;
        uint32_t a2 = *(const uint32_t*)(arow0 + 8);
        uint32_t a3 = *(const uint32_t*)(arow1 + 8);
        #pragma unroll
        for (int nt = 0; nt < 16; nt++) {
            uint2 b = w_sh[(kt * 16 + nt) * 32 + lane];
            hmma(c[nt], a0, a1, a2, a3, b.x, b.y);
        }
    }

    int r0 = row0 + w * 16 + rq;
    int r1 = r0 + 8;
    float sc0 = 1.0f, sc1 = 1.0f;
    if (postscale) {
        if (r0 < n) sc0 = __ldg(&postscale[r0]);
        if (r1 < n) sc1 = __ldg(&postscale[r1]);
    }
    #pragma unroll
    for (int nt = 0; nt < 16; nt++) {
        int col = nt * 8 + kq;
        float2 bv = *(const float2*)&B[col];
        float o00 = fmaxf(c[nt][0] + bv.x, 0.0f) * sc0;
        float o01 = fmaxf(c[nt][1] + bv.y, 0.0f) * sc0;
        float o10 = fmaxf(c[nt][2] + bv.x, 0.0f) * sc1;
        float o11 = fmaxf(c[nt][3] + bv.y, 0.0f) * sc1;
        if (HALF_OUT) {
            if (r0 < n) {
                __half2 p = __floats2half2_rn(o00, o01);
                *(uint32_t*)((__half*)outv + (long)r0 * 128 + col) = *(uint32_t*)&p;
            }
            if (r1 < n) {
                __half2 p = __floats2half2_rn(o10, o11);
                *(uint32_t*)((__half*)outv + (long)r1 * 128 + col) = *(uint32_t*)&p;
            }
        } else {
            if (r0 < n)
                *(float2*)((float*)outv + (long)r0 * 128 + col) = make_float2(o00, o01);
            if (r1 < n)
                *(float2*)((float*)outv + (long)r1 * 128 + col) = make_float2(o10, o11);
        }
    }
}

extern "C" void kernel_launch(void* const* d_in, const int* in_sizes, int n_in,
                              void* d_out, int out_size) {
    const float* x_raw = (const float*)d_in[0];
    const int*   src   = (const int*)d_in[1];
    const int*   dst   = (const int*)d_in[2];
    const float* Wp    = (const float*)d_in[3];
    const float* bp    = (const float*)d_in[4];
    const float* Wl    = (const float*)d_in[5];
    const float* bl    = (const float*)d_in[6];
    float* out = (float*)d_out;

    const int N = in_sizes[0] / 64;
    const int E = in_sizes[1];

    __half *h, *agg;
    float *nsrc, *ndst;
    int *dego, *degi, *off, *cur, *csr, *tsum, *btot;
    uint2* wfrag;
    cudaGetSymbolAddress((void**)&h, g_h);
    cudaGetSymbolAddress((void**)&agg, g_agg);
    cudaGetSymbolAddress((void**)&nsrc, g_nsrc);
    cudaGetSymbolAddress((void**)&ndst, g_ndst);
    cudaGetSymbolAddress((void**)&dego, g_dego);
    cudaGetSymbolAddress((void**)&degi, g_degi);
    cudaGetSymbolAddress((void**)&off, g_off);
    cudaGetSymbolAddress((void**)&cur, g_cur);
    cudaGetSymbolAddress((void**)&csr, g_csr);
    cudaGetSymbolAddress((void**)&tsum, g_tsum);
    cudaGetSymbolAddress((void**)&btot, g_btot);
    cudaGetSymbolAddress((void**)&wfrag, g_wfrag);

    const int MMA_SMEM128 = 128 * 136 * 2 + 4096 * 8;
    const int MMA_SMEM64 = 128 * 72 * 2 + 2048 * 8;
    cudaFuncSetAttribute((const void*)gemm_mma_kernel<8, false, true>,
                         cudaFuncAttributeMaxDynamicSharedMemorySize, MMA_SMEM128);
    cudaFuncSetAttribute((const void*)gemm_mma_kernel<8, false, false>,
                         cudaFuncAttributeMaxDynamicSharedMemorySize, MMA_SMEM128);
    cudaFuncSetAttribute((const void*)gemm_mma_kernel<4, true, true>,
                         cudaFuncAttributeMaxDynamicSharedMemorySize, MMA_SMEM64);

    // 0) weight frags + zero degree counters + zero btot (merged)
    prep_kernel<<<(3 * 4096 + 2048 + 255) / 256, 256>>>(
        Wp, Wl, wfrag, (int4*)dego, (int4*)degi, btot);

    // 1) degrees -> norms + CSR(by dst); hierarchical scan
    const int E8 = E >> 3;
    degree_kernel<<<(E8 + 255) / 256, 256>>>(src, dst, dego, degi, E);
    partsum_norm_kernel<<<SCAN_T / 256, 256>>>(degi, dego, tsum, btot, nsrc, ndst, N);
    scanwrite_kernel<<<SCAN_T / 256, 256>>>(degi, tsum, btot, off, cur, N);
    fill_kernel<<<(E8 + 255) / 256, 256>>>(src, dst, cur, csr, E);

    // 2) h = fp16( relu(x_raw @ Wp + bp) * norm_src )  — HMMA, K=64
    const int mma_blocks = (N + 127) / 128;
    gemm_mma_kernel<4, true, true><<<mma_blocks, 256, MMA_SMEM64>>>(
        x_raw, wfrag + 12288, bp, nsrc, h, N);

    // 3) layers: pull then HMMA GEMM
    const int pull_blocks = (N * 32 + 255) / 256;
    for (int l = 0; l < 3; l++) {
        pull_kernel<<<pull_blocks, 256>>>(off, csr, ndst, (const uint2*)h, (uint2*)agg, N);
        const uint2* wf = wfrag + (long)l * 4096;
        const float* bcur = bl + (long)l * 128;
        if (l == 2) {
            gemm_mma_kernel<8, false, false><<<mma_blocks, 256, MMA_SMEM128>>>(
                (const void*)agg, wf, bcur, nullptr, out, N);
        } else {
            gemm_mma_kernel<8, false, true><<<mma_blocks, 256, MMA_SMEM128>>>(
                (const void*)agg, wf, bcur, nsrc, h, N);
        }
    }
}